// round 15
// baseline (speedup 1.0000x reference)
#include <cuda_runtime.h>
#include <cuda_fp16.h>
#include <cstdint>

// 4D conv (VALID, stride 1) + ReLU via mma.sync m16n8k16 fp16 (fp32 accum).
// R12 shape (tile 16x32, warp = 2 rows x 32 px x 32 oc, 2 CTAs/SM) with the
// per-stage __syncthreads replaced by full/empty mbarrier pipelining:
// warps run decoupled; a rotating warp issues stage k after empty[k%3].
// in  : [2,16,8,8,64,64] f32 -> g_xh[b,d1,d2,y,x][c16perm] fp16 (padded tail)
// wgt : [32,16,3,3,3,3]  f32 -> g_wh[ij9][kl9][oc32][c16perm] fp16
// out : [2,32,6,6,62,62] f32

typedef unsigned int u32;

__device__ __half g_xh[2 * 8 * 8 * 64 * 64 * 16 + 8192];
__device__ __half g_wh[9 * 9 * 32 * 16];

// ---------------- merged pre-kernel ----------------

__global__ void pre_kernel(const float* __restrict__ x,
                           const float* __restrict__ wgt) {
    const int bid = blockIdx.x;
    if (bid < 1024) {
        const int id = bid * 256 + threadIdx.x;    // 262144 (2 px each)
        const int xp = id & 31;
        const int y  = (id >> 5) & 63;
        const int d2 = (id >> 11) & 7;
        const int d1 = (id >> 14) & 7;
        const int b  = id >> 17;
        const long sp = ((((long)b * 16) * 8 + d1) * 8 + d2) * 4096 + y * 64 + xp * 2;
        float2 v[16];
#pragma unroll
        for (int c = 0; c < 16; c++)
            v[c] = *(const float2*)(x + sp + (long)c * 262144);
        const long dbase = ((((long)(b * 8 + d1) * 8 + d2) * 64 + y) * 64 + xp * 2) * 16;
#pragma unroll
        for (int pos = 0; pos < 2; pos++) {
            __half2 h[8];
#pragma unroll
            for (int t = 0; t < 4; t++) {
                h[2 * t]     = __floats2half2_rn(pos ? v[2 * t].y     : v[2 * t].x,
                                                 pos ? v[2 * t + 1].y : v[2 * t + 1].x);
                h[2 * t + 1] = __floats2half2_rn(pos ? v[2 * t + 8].y : v[2 * t + 8].x,
                                                 pos ? v[2 * t + 9].y : v[2 * t + 9].x);
            }
            uint4* dst = reinterpret_cast<uint4*>(g_xh + dbase + pos * 16);
            const u32* hu = reinterpret_cast<const u32*>(h);
            dst[0] = make_uint4(hu[0], hu[1], hu[2], hu[3]);
            dst[1] = make_uint4(hu[4], hu[5], hu[6], hu[7]);
        }
    } else {
        const int id = (bid - 1024) * 256 + threadIdx.x;
        if (id < 9 * 9 * 32 * 16) {
            const int p  = id & 15;
            const int oc = (id >> 4) & 31;
            const int kl = (id >> 9) % 9;
            const int ij = (id >> 9) / 9;
            const int t  = p >> 2, u = p & 3;
            const int ch = (u < 2) ? (2 * t + u) : (2 * t + 6 + u);
            const float v = wgt[oc * 1296 + ch * 81 + (ij / 3) * 27 + (ij % 3) * 9
                                + (kl / 3) * 3 + (kl % 3)];
            g_wh[id] = __float2half_rn(v);
        }
    }
}

// ---------------- helpers ----------------

__device__ __forceinline__ void bulk_g2s(u32 dst, const void* src, u32 bytes, u32 mbar) {
    asm volatile(
        "cp.async.bulk.shared::cluster.global.mbarrier::complete_tx::bytes "
        "[%0], [%1], %2, [%3];"
        :: "r"(dst), "l"(src), "r"(bytes), "r"(mbar) : "memory");
}
__device__ __forceinline__ void mbar_init(u32 mbar, u32 cnt) {
    asm volatile("mbarrier.init.shared.b64 [%0], %1;" :: "r"(mbar), "r"(cnt) : "memory");
}
__device__ __forceinline__ void mbar_expect(u32 mbar, u32 bytes) {
    asm volatile("mbarrier.arrive.expect_tx.shared.b64 _, [%0], %1;"
                 :: "r"(mbar), "r"(bytes) : "memory");
}
__device__ __forceinline__ void mbar_arrive(u32 mbar) {
    asm volatile("mbarrier.arrive.shared.b64 _, [%0];" :: "r"(mbar) : "memory");
}
__device__ __forceinline__ void mbar_wait(u32 mbar, u32 parity) {
    u32 done;
    asm volatile(
        "{\n\t.reg .pred p;\n\t"
        "mbarrier.try_wait.parity.acquire.cta.shared::cta.b64 p, [%1], %2;\n\t"
        "selp.b32 %0, 1, 0, p;\n\t}"
        : "=r"(done) : "r"(mbar), "r"(parity) : "memory");
    if (!done) {
        asm volatile(
            "{\n\t.reg .pred P1;\n\t"
            "WL_%=:\n\t"
            "mbarrier.try_wait.parity.acquire.cta.shared::cta.b64 P1, [%0], %1, 0x989680;\n\t"
            "@P1 bra.uni WD_%=;\n\t"
            "bra.uni WL_%=;\n\t"
            "WD_%=:\n\t}"
            :: "r"(mbar), "r"(parity) : "memory");
    }
}

#define MMA_F16(d, a0, a1, a2, a3, b0, b1)                                    \
    asm volatile(                                                             \
        "mma.sync.aligned.m16n8k16.row.col.f32.f16.f16.f32 "                  \
        "{%0,%1,%2,%3}, {%4,%5,%6,%7}, {%8,%9}, {%0,%1,%2,%3};"               \
        : "+f"((d)[0]), "+f"((d)[1]), "+f"((d)[2]), "+f"((d)[3])              \
        : "r"(a0), "r"(a1), "r"(a2), "r"(a3), "r"(b0), "r"(b1))

#define SXH 9792          // 18 rows * 34 pos * 16 halves
#define SWH 4608          // 9 taps * 32 oc * 16 halves
#define BUFH (SXH + SWH)  // 14400 halves = 28800 B
#define STAGE_BYTES 28800u
#define SMEM_BYTES (3 * BUFH * 2)   // 86400 (epilogue xpose 69632 -- fits)

// ---------------- main kernel ----------------

__global__ __launch_bounds__(256, 2)
void conv4d_f16_pipe_kernel(float* __restrict__ out)
{
    extern __shared__ __align__(128) __half smh[];
    __shared__ __align__(8) unsigned long long s_full[3];
    __shared__ __align__(8) unsigned long long s_empty[3];

    const u32 su   = (u32)__cvta_generic_to_shared(smh);
    const u32 mb_f = (u32)__cvta_generic_to_shared(s_full);
    const u32 mb_e = (u32)__cvta_generic_to_shared(s_empty);

    const int tid  = threadIdx.x;
    const int w    = tid >> 5;          // warp 0..7 -> rows 2w, 2w+1
    const int lane = tid & 31;
    const int lg   = lane >> 2;
    const int tg   = lane & 3;
    const int w2   = 2 * w;

    const int x0 = 32 * blockIdx.x;     // 0, 32
    const int y0 = 16 * blockIdx.y;     // 0, 16, 32, 48
    const int zb = blockIdx.z;
    const int b  = zb / 36;
    const int zr = zb % 36;
    const int z1 = zr / 6, z2 = zr % 6;

    if (tid == 0) {
#pragma unroll
        for (int s = 0; s < 3; s++) {
            mbar_init(mb_f + s * 8, 1u);    // TMA completion (expect_tx)
            mbar_init(mb_e + s * 8, 8u);    // one arrive per warp
        }
    }
    __syncthreads();

#define ISSUE(K) do {                                                         \
    const int i_ = (K) / 3, j_ = (K) % 3;                                     \
    const long xgb = (((long)(b * 8 + z1 + i_) * 8 + (z2 + j_)) * 4096) * 16; \
    const u32 bufu = su + (u32)((K) % 3) * (BUFH * 2);                        \
    const u32 m = mb_f + (u32)((K) % 3) * 8;                                  \
    mbar_expect(m, STAGE_BYTES);                                              \
    const __half* xsrc = g_xh + xgb + ((long)y0 * 64 + x0) * 16;              \
    for (int ry = 0; ry < 18; ry++)                                           \
        bulk_g2s(bufu + ry * 1088, xsrc + (long)ry * 1024, 1088, m);          \
    bulk_g2s(bufu + SXH * 2, g_wh + (K) * 4608, 9216, m);                     \
} while (0)

    if (tid == 0) { ISSUE(0); ISSUE(1); ISSUE(2); }

    float acc[4][4][4];
#pragma unroll
    for (int mt = 0; mt < 4; mt++)
#pragma unroll
        for (int n = 0; n < 4; n++)
#pragma unroll
            for (int r = 0; r < 4; r++)
                acc[mt][n][r] = 0.f;

    const int poff = lg * 16 + tg * 4;

#pragma unroll 1
    for (int ij = 0; ij < 9; ij++) {
        const u32 par = (u32)((ij / 3) & 1);
        mbar_wait(mb_f + (u32)(ij % 3) * 8, par);

        const __half* __restrict__ sx = smh + (ij % 3) * BUFH;
        const __half* __restrict__ sw = sx + SXH;

#pragma unroll
        for (int ll = 0; ll < 3; ll++) {
            // A block: 4 rows x 2 x-halves x 2 uint2, reused across kk
            uint2 Ar[4][2][2];
#pragma unroll
            for (int r = 0; r < 4; r++) {
                const __half* axp = sx + ((w2 + r) * 34 + ll) * 16 + poff;
                Ar[r][0][0] = *(const uint2*)(axp);
                Ar[r][0][1] = *(const uint2*)(axp + 128);
                Ar[r][1][0] = *(const uint2*)(axp + 256);
                Ar[r][1][1] = *(const uint2*)(axp + 384);
            }
#pragma unroll
            for (int kk = 0; kk < 3; kk++) {
                const __half* swp = sw + (kk * 3 + ll) * 512 + poff;
                const uint2 B0 = *(const uint2*)(swp);
                const uint2 B1 = *(const uint2*)(swp + 128);
                const uint2 B2 = *(const uint2*)(swp + 256);
                const uint2 B3 = *(const uint2*)(swp + 384);
#pragma unroll
                for (int mt = 0; mt < 4; mt++) {
                    const int r  = kk + (mt >> 1);
                    const int xh = mt & 1;
                    const u32 a0 = Ar[r][xh][0].x, a1 = Ar[r][xh][1].x;
                    const u32 a2 = Ar[r][xh][0].y, a3 = Ar[r][xh][1].y;
                    MMA_F16(acc[mt][0], a0, a1, a2, a3, B0.x, B0.y);
                    MMA_F16(acc[mt][1], a0, a1, a2, a3, B1.x, B1.y);
                    MMA_F16(acc[mt][2], a0, a1, a2, a3, B2.x, B2.y);
                    MMA_F16(acc[mt][3], a0, a1, a2, a3, B3.x, B3.y);
                }
            }
        }

        // done reading buffer ij%3 (reads landed in regs before last MMA issue)
        if (lane == 0) mbar_arrive(mb_e + (u32)(ij % 3) * 8);

        // rotating issuer: warp (ij+3)&7 refills buffer ij%3 with stage ij+3
        if (ij < 6 && lane == 0 && w == ((ij + 3) & 7)) {
            mbar_wait(mb_e + (u32)(ij % 3) * 8, par);   // all 8 warps done
            ISSUE(ij + 3);
        }
    }

    // ---- epilogue: smem transpose (stride 34 -- even) -> coalesced float2
    __syncthreads();
    float* st = reinterpret_cast<float*>(smh);
#pragma unroll
    for (int mt = 0; mt < 4; mt++) {
        const int yl  = w2 + (mt >> 1);
        const int pxb = 16 * (mt & 1) + lg;
#pragma unroll
        for (int n = 0; n < 4; n++) {
            const int ocb = 8 * n + 2 * tg;
            st[(yl * 32 + ocb)     * 34 + pxb]     = acc[mt][n][0];
            st[(yl * 32 + ocb + 1) * 34 + pxb]     = acc[mt][n][1];
            st[(yl * 32 + ocb)     * 34 + pxb + 8] = acc[mt][n][2];
            st[(yl * 32 + ocb + 1) * 34 + pxb + 8] = acc[mt][n][3];
        }
    }
    __syncthreads();

    const long ob = (long)b * 4428288 + (z1 * 6 + z2) * 3844;
#pragma unroll
    for (int k = 0; k < 32; k++) {
        const int v  = k * 256 + tid;          // 8192 float2 units
        const int p  = v & 15;                 // 16 float2 per 32-px row
        const int oc = (v >> 4) & 31;
        const int y  = v >> 9;
        const int gy = y0 + y;
        const int px = x0 + 2 * p;
        if (gy < 62 && px < 62) {
            float2 val = *(const float2*)(st + (y * 32 + oc) * 34 + 2 * p);
            val.x = fmaxf(val.x, 0.f);
            val.y = fmaxf(val.y, 0.f);
            *(float2*)(out + ob + (long)oc * 138384 + (long)gy * 62 + px) = val;
        }
    }
}

extern "C" void kernel_launch(void* const* d_in, const int* in_sizes, int n_in,
                              void* d_out, int out_size)
{
    const float* x   = (const float*)d_in[0];
    const float* wgt = (const float*)d_in[1];
    float* out = (float*)d_out;

    cudaFuncSetAttribute(conv4d_f16_pipe_kernel,
                         cudaFuncAttributeMaxDynamicSharedMemorySize, SMEM_BYTES);

    pre_kernel<<<1186, 256>>>(x, wgt);
    conv4d_f16_pipe_kernel<<<dim3(2, 4, 72), 256, SMEM_BYTES>>>(out);
}

// round 17
// speedup vs baseline: 1.0626x; 1.0626x over previous
#include <cuda_runtime.h>
#include <cuda_fp16.h>
#include <cstdint>

// 4D conv (VALID, stride 1) + ReLU via mma.sync m16n8k16 fp16 (fp32 accum),
// TMA bulk staging + mbarrier (triple buffer, sync per stage) -- R10 main
// kernel (measured best) -- with a merged float4-vectorized pre-pass.
// FIX vs R16: consistent issue schedule (prologue 0,1,2; loop refills ij+3).
// in  : [2,16,8,8,64,64] f32 -> g_xh[b,d1,d2,y,x][c16perm] fp16 (padded tail)
// wgt : [32,16,3,3,3,3]  f32 -> g_wh[ij9][kl9][oc32][c16perm] fp16
// out : [2,32,6,6,62,62] f32

typedef unsigned int u32;

__device__ __half g_xh[2 * 8 * 8 * 64 * 64 * 16 + 8192];   // pad
__device__ __half g_wh[9 * 9 * 32 * 16];

// ---------------- merged pre-kernel (float4 x-reads, 4 px/thread) ----------

__global__ void pre_kernel(const float* __restrict__ x,
                           const float* __restrict__ wgt) {
    const int bid = blockIdx.x;
    if (bid < 512) {
        const int id = bid * 256 + threadIdx.x;    // 131072 threads, 4 px each
        const int xq = id & 15;                    // 4-px group
        const int y  = (id >> 4) & 63;
        const int d2 = (id >> 10) & 7;
        const int d1 = (id >> 13) & 7;
        const int b  = id >> 16;
        const long sp = ((((long)b * 16) * 8 + d1) * 8 + d2) * 4096 + y * 64 + xq * 4;
        float4 v[16];
#pragma unroll
        for (int c = 0; c < 16; c++)
            v[c] = *(const float4*)(x + sp + (long)c * 262144);
        const long dbase = ((((long)(b * 8 + d1) * 8 + d2) * 64 + y) * 64 + xq * 4) * 16;
#pragma unroll
        for (int q = 0; q < 4; q++) {
            __half2 h[8];
#pragma unroll
            for (int t = 0; t < 4; t++) {
                const float a0 = q == 0 ? v[2*t].x   : q == 1 ? v[2*t].y   : q == 2 ? v[2*t].z   : v[2*t].w;
                const float a1 = q == 0 ? v[2*t+1].x : q == 1 ? v[2*t+1].y : q == 2 ? v[2*t+1].z : v[2*t+1].w;
                const float a2 = q == 0 ? v[2*t+8].x : q == 1 ? v[2*t+8].y : q == 2 ? v[2*t+8].z : v[2*t+8].w;
                const float a3 = q == 0 ? v[2*t+9].x : q == 1 ? v[2*t+9].y : q == 2 ? v[2*t+9].z : v[2*t+9].w;
                h[2 * t]     = __floats2half2_rn(a0, a1);
                h[2 * t + 1] = __floats2half2_rn(a2, a3);
            }
            uint4* dst = reinterpret_cast<uint4*>(g_xh + dbase + q * 16);
            const u32* hu = reinterpret_cast<const u32*>(h);
            dst[0] = make_uint4(hu[0], hu[1], hu[2], hu[3]);
            dst[1] = make_uint4(hu[4], hu[5], hu[6], hu[7]);
        }
    } else {
        const int id = (bid - 512) * 256 + threadIdx.x;
        if (id < 9 * 9 * 32 * 16) {
            const int p  = id & 15;
            const int oc = (id >> 4) & 31;
            const int kl = (id >> 9) % 9;
            const int ij = (id >> 9) / 9;
            const int t  = p >> 2, u = p & 3;
            const int ch = (u < 2) ? (2 * t + u) : (2 * t + 6 + u);   // perm
            const float v = wgt[oc * 1296 + ch * 81 + (ij / 3) * 27 + (ij % 3) * 9
                                + (kl / 3) * 3 + (kl % 3)];
            g_wh[id] = __float2half_rn(v);
        }
    }
}

// ---------------- helpers ----------------

__device__ __forceinline__ void bulk_g2s(u32 dst, const void* src, u32 bytes, u32 mbar) {
    asm volatile(
        "cp.async.bulk.shared::cluster.global.mbarrier::complete_tx::bytes "
        "[%0], [%1], %2, [%3];"
        :: "r"(dst), "l"(src), "r"(bytes), "r"(mbar) : "memory");
}
__device__ __forceinline__ void mbar_init(u32 mbar, u32 cnt) {
    asm volatile("mbarrier.init.shared.b64 [%0], %1;" :: "r"(mbar), "r"(cnt) : "memory");
}
__device__ __forceinline__ void mbar_expect(u32 mbar, u32 bytes) {
    asm volatile("mbarrier.arrive.expect_tx.shared.b64 _, [%0], %1;"
                 :: "r"(mbar), "r"(bytes) : "memory");
}
__device__ __forceinline__ void mbar_wait(u32 mbar, u32 parity) {
    u32 done;
    asm volatile(
        "{\n\t.reg .pred p;\n\t"
        "mbarrier.try_wait.parity.acquire.cta.shared::cta.b64 p, [%1], %2;\n\t"
        "selp.b32 %0, 1, 0, p;\n\t}"
        : "=r"(done) : "r"(mbar), "r"(parity) : "memory");
    if (!done) {
        asm volatile(
            "{\n\t.reg .pred P1;\n\t"
            "WL_%=:\n\t"
            "mbarrier.try_wait.parity.acquire.cta.shared::cta.b64 P1, [%0], %1, 0x989680;\n\t"
            "@P1 bra.uni WD_%=;\n\t"
            "bra.uni WL_%=;\n\t"
            "WD_%=:\n\t}"
            :: "r"(mbar), "r"(parity) : "memory");
    }
}

#define MMA_F16(d, a0, a1, a2, a3, b0, b1)                                    \
    asm volatile(                                                             \
        "mma.sync.aligned.m16n8k16.row.col.f32.f16.f16.f32 "                  \
        "{%0,%1,%2,%3}, {%4,%5,%6,%7}, {%8,%9}, {%0,%1,%2,%3};"               \
        : "+f"((d)[0]), "+f"((d)[1]), "+f"((d)[2]), "+f"((d)[3])              \
        : "r"(a0), "r"(a1), "r"(a2), "r"(a3), "r"(b0), "r"(b1))

#define SXH 9792          // 18 rows * 34 pos * 16 halves
#define SWH 4608          // 9 taps * 32 oc * 16 halves
#define BUFH (SXH + SWH)  // 14400 halves = 28800 B
#define STAGE_BYTES 28800u
#define SMEM_BYTES (3 * BUFH * 2)   // 86400

// ---------------- main kernel (R10 -- measured best) ----------------

__global__ __launch_bounds__(256, 2)
void conv4d_f16_tma_kernel(float* __restrict__ out)
{
    extern __shared__ __align__(128) __half smh[];
    __shared__ __align__(8) unsigned long long s_mbar[3];

    const u32 su = (u32)__cvta_generic_to_shared(smh);
    const u32 mb = (u32)__cvta_generic_to_shared(s_mbar);

    const int tid  = threadIdx.x;
    const int w    = tid >> 5;          // warp 0..7 -> rows 2w, 2w+1
    const int lane = tid & 31;
    const int lg   = lane >> 2;
    const int tg   = lane & 3;
    const int w2   = 2 * w;

    const int x0 = 32 * blockIdx.x;     // 0, 32
    const int y0 = 16 * blockIdx.y;     // 0, 16, 32, 48
    const int zb = blockIdx.z;
    const int b  = zb / 36;
    const int zr = zb % 36;
    const int z1 = zr / 6, z2 = zr % 6;

    if (tid == 0) {
        mbar_init(mb,      1u);
        mbar_init(mb + 8,  1u);
        mbar_init(mb + 16, 1u);
    }
    __syncthreads();

#define ISSUE(K) do {                                                         \
    const int i_ = (K) / 3, j_ = (K) % 3;                                     \
    const long xgb = (((long)(b * 8 + z1 + i_) * 8 + (z2 + j_)) * 4096) * 16; \
    const u32 bufu = su + (u32)((K) % 3) * (BUFH * 2);                        \
    const u32 m = mb + (u32)((K) % 3) * 8;                                    \
    mbar_expect(m, STAGE_BYTES);                                              \
    const __half* xsrc = g_xh + xgb + ((long)y0 * 64 + x0) * 16;              \
    for (int ry = 0; ry < 18; ry++)                                           \
        bulk_g2s(bufu + ry * 1088, xsrc + (long)ry * 1024, 1088, m);          \
    bulk_g2s(bufu + SXH * 2, g_wh + (K) * 4608, 9216, m);                     \
} while (0)

    if (tid == 0) { ISSUE(0); ISSUE(1); ISSUE(2); }

    float acc[4][4][4];
#pragma unroll
    for (int mt = 0; mt < 4; mt++)
#pragma unroll
        for (int n = 0; n < 4; n++)
#pragma unroll
            for (int r = 0; r < 4; r++)
                acc[mt][n][r] = 0.f;

    const int poff = lg * 16 + tg * 4;

#pragma unroll 1
    for (int ij = 0; ij < 9; ij++) {
        mbar_wait(mb + (u32)(ij % 3) * 8, (u32)((ij / 3) & 1));

        const __half* __restrict__ sx = smh + (ij % 3) * BUFH;
        const __half* __restrict__ sw = sx + SXH;

#pragma unroll
        for (int kl = 0; kl < 9; kl++) {
            const int kk = kl / 3, ll = kl % 3;
            const __half* axp = sx + ((w2 + kk) * 34 + ll) * 16 + poff;

            uint2 A[4][2];
            A[0][0] = *(const uint2*)(axp);
            A[0][1] = *(const uint2*)(axp + 128);
            A[1][0] = *(const uint2*)(axp + 256);
            A[1][1] = *(const uint2*)(axp + 384);
            A[2][0] = *(const uint2*)(axp + 544);
            A[2][1] = *(const uint2*)(axp + 672);
            A[3][0] = *(const uint2*)(axp + 800);
            A[3][1] = *(const uint2*)(axp + 928);

            const __half* swp = sw + kl * 512 + poff;
            const uint2 B0 = *(const uint2*)(swp);
            const uint2 B1 = *(const uint2*)(swp + 128);
            const uint2 B2 = *(const uint2*)(swp + 256);
            const uint2 B3 = *(const uint2*)(swp + 384);

#pragma unroll
            for (int mt = 0; mt < 4; mt++) {
                const u32 a0 = A[mt][0].x, a1 = A[mt][1].x;
                const u32 a2 = A[mt][0].y, a3 = A[mt][1].y;
                MMA_F16(acc[mt][0], a0, a1, a2, a3, B0.x, B0.y);
                MMA_F16(acc[mt][1], a0, a1, a2, a3, B1.x, B1.y);
                MMA_F16(acc[mt][2], a0, a1, a2, a3, B2.x, B2.y);
                MMA_F16(acc[mt][3], a0, a1, a2, a3, B3.x, B3.y);
            }
        }

        __syncthreads();                 // all warps done reading buf ij%3
        if (ij + 3 < 9 && tid == 0) ISSUE(ij + 3);
    }

    // ---- epilogue: ReLU + direct stores (R10 style)
    const long ob = (long)b * 4428288 + (z1 * 6 + z2) * 3844;
#pragma unroll
    for (int mt = 0; mt < 4; mt++) {
        const int y = y0 + w2 + (mt >> 1);
        if (y >= 62) continue;
        const int px0 = x0 + (mt & 1) * 16 + lg;
        const int px8 = px0 + 8;
#pragma unroll
        for (int n = 0; n < 4; n++) {
            const int oc = n * 8 + 2 * tg;
            const long o0 = ob + (long)oc * 138384 + (long)y * 62;
            if (px0 < 62) {
                out[o0 + px0]          = fmaxf(acc[mt][n][0], 0.f);
                out[o0 + 138384 + px0] = fmaxf(acc[mt][n][1], 0.f);
            }
            if (px8 < 62) {
                out[o0 + px8]          = fmaxf(acc[mt][n][2], 0.f);
                out[o0 + 138384 + px8] = fmaxf(acc[mt][n][3], 0.f);
            }
        }
    }
}

extern "C" void kernel_launch(void* const* d_in, const int* in_sizes, int n_in,
                              void* d_out, int out_size)
{
    const float* x   = (const float*)d_in[0];
    const float* wgt = (const float*)d_in[1];
    float* out = (float*)d_out;

    cudaFuncSetAttribute(conv4d_f16_tma_kernel,
                         cudaFuncAttributeMaxDynamicSharedMemorySize, SMEM_BYTES);

    pre_kernel<<<674, 256>>>(x, wgt);
    conv4d_f16_tma_kernel<<<dim3(2, 4, 72), 256, SMEM_BYTES>>>(out);
}